// round 12
// baseline (speedup 1.0000x reference)
#include <cuda_runtime.h>
#include <cstddef>

// Problem constants
#define NVQ   2000          // number of query points
#define RDIM  128           // spatial basis functions
#define KM1   30            // K - 1
#define KTOT  31            // K
#define COV_ROW 3840        // RDIM * KM1

// Tiling
#define VT      128         // v per CTA tile
#define ISPLIT  4           // i-range split (tail smoothing)
#define ICHUNK  (RDIM / ISPLIT)   // 32
#define XS_PITCH 132        // 128 + 4 pad -> conflict-free LDS.128 (bank stride 4)
#define CR_PITCH 32         // 30 + 2 pad -> 16B-aligned l-quads, all 32 banks
#define MEAN_SZ (NVQ * KTOT)        // 62000 floats, then cov region

#define FMA_L4(Y, a, C) do {                      \
    (Y)[0] = fmaf((a), (C).x, (Y)[0]);            \
    (Y)[1] = fmaf((a), (C).y, (Y)[1]);            \
    (Y)[2] = fmaf((a), (C).z, (Y)[2]);            \
    (Y)[3] = fmaf((a), (C).w, (Y)[3]);            \
} while (0)

// ---------------------------------------------------------------------------
// Kernel 1: zero the whole cov region, set [v][0][0] = 0.5 (sigma2_mu).
// cov region is accumulated into with atomicAdd by the main kernel, so it
// must start at exact zeros. Borders ([.,0,:], [.,1:,0]) stay zero.
// ---------------------------------------------------------------------------
__global__ void init_cov_kernel(float* __restrict__ out) {
    int idx = blockIdx.x * blockDim.x + threadIdx.x;
    const int total = NVQ * KTOT * KTOT;
    if (idx < total) {
        int q = idx % (KTOT * KTOT);
        out[MEAN_SZ + idx] = (q == 0) ? 0.5f : 0.0f;
    }
}

// ---------------------------------------------------------------------------
// Kernel 2: Post_mean_coefs (2000 x 31). col 0 = C_mu, cols 1..30 = X @ W.
// 7.7 MFLOP -> negligible.
// ---------------------------------------------------------------------------
__global__ void mean_kernel(const float* __restrict__ Xi,   // [128][2000]
                            const float* __restrict__ Wm,   // [3840]
                            const float* __restrict__ Cmu,  // [2000]
                            float* __restrict__ out) {
    int idx = blockIdx.x * blockDim.x + threadIdx.x;
    if (idx >= NVQ * KTOT) return;
    int v = idx / KTOT;
    int c = idx - v * KTOT;
    if (c == 0) { out[idx] = Cmu[v]; return; }
    float s = 0.0f;
#pragma unroll 8
    for (int i = 0; i < RDIM; i++)
        s = fmaf(Xi[i * NVQ + v], Wm[i * KM1 + (c - 1)], s);
    out[idx] = s;
}

// ---------------------------------------------------------------------------
// Kernel 3 (the hot one): cov[v,k,l] = sum_i x[v,i] * (sum_j x[v,j]*Crow_ik[j,l])
// Grid: (ceil(NV/VT)=16, k=30, i-chunk=4) = 1920 CTAs. Block: 256 threads.
// Per thread: 4v x 4l register tile; thread v's = vg + 32*m (conflict-free
// LDS.128 on Xs), l's = lg*4..+3 (conflict-free LDS.128 on Cr).
// One 15 KB C row per i, register double-buffered through SMEM.
// Epilogue: atomicAdd partial tile into zeroed cov region.
// ---------------------------------------------------------------------------
__global__ __launch_bounds__(256, 2)
void cov_kernel(const float* __restrict__ Xi,    // [128][2000]
                const float* __restrict__ Cov,   // [3840][3840]
                float* __restrict__ out) {
    extern __shared__ float smem[];
    float* Xs = smem;                         // [128][XS_PITCH]
    float* Cr = smem + RDIM * XS_PITCH;       // [128][CR_PITCH]

    const int t     = threadIdx.x;
    const int lg    = t & 7;                  // 8 l-groups
    const int vg    = t >> 3;                 // 32 v-groups
    const int vbase = blockIdx.x * VT;
    const int k     = blockIdx.y;
    const int i0    = blockIdx.z * ICHUNK;
    const int lbase = lg * 4;

    // Load/transpose X tile: Xs[vl][j] = Xi[j][vbase+vl]; zero-fill past NV.
    for (int idx = t; idx < RDIM * VT; idx += 256) {
        int j  = idx >> 7;
        int vl = idx & 127;
        int v  = vbase + vl;
        Xs[vl * XS_PITCH + j] = (v < NVQ) ? Xi[j * NVQ + v] : 0.0f;
    }
    // Zero Cr padding columns (l = 30, 31) once — never overwritten after.
    if (t < RDIM) {
        Cr[t * CR_PITCH + 30] = 0.0f;
        Cr[t * CR_PITCH + 31] = 0.0f;
    }

    // Stage first C row into registers (3840 = 15 * 256 exactly).
    float stage[15];
    {
        const float* row = Cov + (size_t)(i0 * KM1 + k) * COV_ROW;
#pragma unroll
        for (int s = 0; s < 15; s++) stage[s] = row[t + 256 * s];
    }
    __syncthreads();   // Xs + padding visible
#pragma unroll
    for (int s = 0; s < 15; s++) {
        int lin = t + 256 * s;
        Cr[(lin / 30) * CR_PITCH + (lin % 30)] = stage[s];
    }
    __syncthreads();

    float acc[4][4] = {};

    for (int ii = 0; ii < ICHUNK; ii++) {
        const int i = i0 + ii;

        // Prefetch next C row into registers (latency hidden by compute).
        if (ii + 1 < ICHUNK) {
            const float* row = Cov + (size_t)((i + 1) * KM1 + k) * COV_ROW;
#pragma unroll
            for (int s = 0; s < 15; s++) stage[s] = row[t + 256 * s];
        }

        // y[m][ll] = sum_j Xs[v_m][j] * Cr[j][lbase+ll]
        float y[4][4] = {};
#pragma unroll 4
        for (int j = 0; j < RDIM; j += 4) {
            const float4 cf0 = *(const float4*)(Cr + (j + 0) * CR_PITCH + lbase);
            const float4 cf1 = *(const float4*)(Cr + (j + 1) * CR_PITCH + lbase);
            const float4 cf2 = *(const float4*)(Cr + (j + 2) * CR_PITCH + lbase);
            const float4 cf3 = *(const float4*)(Cr + (j + 3) * CR_PITCH + lbase);
#pragma unroll
            for (int m = 0; m < 4; m++) {
                const float4 xf = *(const float4*)(Xs + (vg + 32 * m) * XS_PITCH + j);
                FMA_L4(y[m], xf.x, cf0);
                FMA_L4(y[m], xf.y, cf1);
                FMA_L4(y[m], xf.z, cf2);
                FMA_L4(y[m], xf.w, cf3);
            }
        }

        // acc += x[v,i] * y
#pragma unroll
        for (int m = 0; m < 4; m++) {
            const float xi = Xs[(vg + 32 * m) * XS_PITCH + i];
#pragma unroll
            for (int ll = 0; ll < 4; ll++)
                acc[m][ll] = fmaf(xi, y[m][ll], acc[m][ll]);
        }

        __syncthreads();   // all reads of Cr done
        if (ii + 1 < ICHUNK) {
#pragma unroll
            for (int s = 0; s < 15; s++) {
                int lin = t + 256 * s;
                Cr[(lin / 30) * CR_PITCH + (lin % 30)] = stage[s];
            }
        }
        __syncthreads();   // Cr refilled
    }

    // Epilogue: accumulate partial tile into Post_cov_mats[v][k+1][l+1].
#pragma unroll
    for (int m = 0; m < 4; m++) {
        const int v = vbase + vg + 32 * m;
        if (v < NVQ) {
#pragma unroll
            for (int ll = 0; ll < 4; ll++) {
                const int l = lbase + ll;
                if (l < KM1) {
                    atomicAdd(out + MEAN_SZ + (size_t)v * (KTOT * KTOT)
                                  + (k + 1) * KTOT + (l + 1),
                              acc[m][ll]);
                }
            }
        }
    }
}

// ---------------------------------------------------------------------------
// kernel_launch: init -> means -> cov (same stream, in-order; graph-capturable:
// only kernel launches + one idempotent cudaFuncSetAttribute, no allocs).
// ---------------------------------------------------------------------------
extern "C" void kernel_launch(void* const* d_in, const int* in_sizes, int n_in,
                              void* d_out, int out_size) {
    const float* Xi  = (const float*)d_in[0];   // Xi_evals        (128*2000)
    const float* Wm  = (const float*)d_in[1];   // vec_W_post_mean (3840)
    const float* Cov = (const float*)d_in[2];   // vec_W_post_cov  (3840*3840)
    const float* Cmu = (const float*)d_in[3];   // C_mu            (2000)
    float* out = (float*)d_out;

    (void)in_sizes; (void)n_in; (void)out_size;

    const int covTot = NVQ * KTOT * KTOT;
    init_cov_kernel<<<(covTot + 255) / 256, 256>>>(out);
    mean_kernel<<<(NVQ * KTOT + 255) / 256, 256>>>(Xi, Wm, Cmu, out);

    const int smemB = (RDIM * XS_PITCH + RDIM * CR_PITCH) * (int)sizeof(float); // 83968 B
    cudaFuncSetAttribute(cov_kernel, cudaFuncAttributeMaxDynamicSharedMemorySize, smemB);

    dim3 grid((NVQ + VT - 1) / VT, KM1, ISPLIT);  // (16, 30, 4)
    cov_kernel<<<grid, 256, smemB>>>(Xi, Cov, out);
}

// round 13
// speedup vs baseline: 1.1509x; 1.1509x over previous
#include <cuda_runtime.h>
#include <cstddef>

// Problem constants
#define NVQ     2000
#define RDIM    128
#define KM1     30
#define KTOT    31
#define COV_ROW 3840            // RDIM * KM1
#define NPAIR   8256            // 128*129/2 pairs (i >= j)
#define NCHUNK  129             // NPAIR / 64
#define ZSPLIT  3
#define CHUNKS_PER_Z 43         // 129 / 3
#define VT      128             // v per CTA tile
#define XS_PITCH 128            // Xs[j][v] row pitch
#define PS_PITCH 68             // Ps[v][pp] row pitch (64 + 4 pad)
#define DC_PITCH 32             // D[.][pair][l] pitch (30 + 2 pad)
#define MEAN_SZ (NVQ * KTOT)

#define FMA_L4(Y, a, C) do {                      \
    (Y)[0] = fmaf((a), (C).x, (Y)[0]);            \
    (Y)[1] = fmaf((a), (C).y, (Y)[1]);            \
    (Y)[2] = fmaf((a), (C).z, (Y)[2]);            \
    (Y)[3] = fmaf((a), (C).w, (Y)[3]);            \
} while (0)

// Scratch (static device globals: allowed; no runtime allocation).
__device__ float    g_D[(size_t)KM1 * NPAIR * DC_PITCH];   // ~31.7 MB
__device__ unsigned g_pairIJ[NPAIR];                       // packed (i<<16)|j

// ---------------------------------------------------------------------------
// Zero cov region; set [v][0][0] = 0.5 (sigma2_mu). Borders stay zero.
// ---------------------------------------------------------------------------
__global__ void init_cov_kernel(float* __restrict__ out) {
    int idx = blockIdx.x * blockDim.x + threadIdx.x;
    const int total = NVQ * KTOT * KTOT;
    if (idx < total) {
        int q = idx % (KTOT * KTOT);
        out[MEAN_SZ + idx] = (q == 0) ? 0.5f : 0.0f;
    }
}

// ---------------------------------------------------------------------------
// Post_mean_coefs (2000 x 31): col 0 = C_mu, cols 1..30 = X @ W. Negligible.
// ---------------------------------------------------------------------------
__global__ void mean_kernel(const float* __restrict__ Xi,
                            const float* __restrict__ Wm,
                            const float* __restrict__ Cmu,
                            float* __restrict__ out) {
    int idx = blockIdx.x * blockDim.x + threadIdx.x;
    if (idx >= NVQ * KTOT) return;
    int v = idx / KTOT;
    int c = idx - v * KTOT;
    if (c == 0) { out[idx] = Cmu[v]; return; }
    float s = 0.0f;
#pragma unroll 8
    for (int i = 0; i < RDIM; i++)
        s = fmaf(Xi[i * NVQ + v], Wm[i * KM1 + (c - 1)], s);
    out[idx] = s;
}

// ---------------------------------------------------------------------------
// Pair enumeration table: pair p = i*(i+1)/2 + j, i >= j.
// ---------------------------------------------------------------------------
__global__ void pair_table_kernel() {
    int i = blockIdx.x;
    int j = threadIdx.x;
    if (j <= i)
        g_pairIJ[i * (i + 1) / 2 + j] = ((unsigned)i << 16) | (unsigned)j;
}

// ---------------------------------------------------------------------------
// Symmetrized matrix: D[k][pair][l] = C[(ik),(jl)] + (i!=j) * C[(jk),(il)].
// One warp per (pair, k); lane = l. Each C element is read exactly once.
// ---------------------------------------------------------------------------
__global__ void build_D_kernel(const float* __restrict__ Cov) {
    int gwarp = (blockIdx.x * blockDim.x + threadIdx.x) >> 5;
    int lane  = threadIdx.x & 31;
    if (gwarp >= NPAIR * KM1) return;
    int pair = gwarp / KM1;
    int k    = gwarp - pair * KM1;
    unsigned ij = g_pairIJ[pair];
    int i = (int)(ij >> 16);
    int j = (int)(ij & 0xffff);
    float v = 0.0f;
    if (lane < KM1) {
        v = Cov[(size_t)(i * KM1 + k) * COV_ROW + j * KM1 + lane];
        if (i != j)
            v += Cov[(size_t)(j * KM1 + k) * COV_ROW + i * KM1 + lane];
    }
    g_D[((size_t)k * NPAIR + pair) * DC_PITCH + lane] = v;   // pad lanes -> 0
}

// ---------------------------------------------------------------------------
// Hot kernel: cov[v,k,l] = sum_pair Ps[v,pair] * D[k][pair][l]
// Grid (16 vtiles, 30 k, 3 z) = 1440 CTAs, 256 threads.
// Per chunk of 64 pairs: stage D row-block (register prefetched) + compute
// Ps[v][pp] = x[v,i]*x[v,j] from the resident X tile; then the same
// 4v x 4l register-tile GEMM loop that hit the FFMA roofline in R12.
// ---------------------------------------------------------------------------
__global__ __launch_bounds__(256, 2)
void cov_pair_kernel(const float* __restrict__ Xi,   // [128][2000]
                     float* __restrict__ out) {
    extern __shared__ float smem[];
    float* Xs = smem;                               // [128 j][128 v]
    float* Ps = smem + RDIM * XS_PITCH;             // [128 v][PS_PITCH]
    float* Dc = Ps + VT * PS_PITCH;                 // [64 pp][DC_PITCH]

    const int t     = threadIdx.x;
    const int lg    = t & 7;
    const int vg    = t >> 3;
    const int vbase = blockIdx.x * VT;
    const int k     = blockIdx.y;
    const int c0    = blockIdx.z * CHUNKS_PER_Z;
    const int lbase = lg * 4;

    const float* Dk = g_D + (size_t)k * NPAIR * DC_PITCH;

    // Load X tile transposed-free: Xs[j][v] = Xi[j][vbase+v] (coalesced).
#pragma unroll 8
    for (int s = 0; s < (RDIM * VT) / 256; s++) {
        int idx = t + 256 * s;
        int j = idx >> 7, v = idx & 127;
        int gv = vbase + v;
        Xs[j * XS_PITCH + v] = (gv < NVQ) ? Xi[j * NVQ + gv] : 0.0f;
    }

    // Prefetch first D chunk into registers (independent of Xs).
    float dst[8];
    {
        const float* src = Dk + (size_t)c0 * 64 * DC_PITCH;
#pragma unroll
        for (int s = 0; s < 8; s++) dst[s] = src[t + 256 * s];
    }
    __syncthreads();   // Xs visible

    // Stage first chunk: Dc + Ps.
    {
#pragma unroll
        for (int s = 0; s < 8; s++) Dc[t + 256 * s] = dst[s];
        const int pairBase = c0 * 64;
#pragma unroll 4
        for (int s = 0; s < 32; s++) {
            int idx = t + 256 * s;
            int v = idx & 127, pp = idx >> 7;
            unsigned ij = g_pairIJ[pairBase + pp];
            int i = (int)(ij >> 16), j = (int)(ij & 0xffff);
            Ps[v * PS_PITCH + pp] = Xs[i * XS_PITCH + v] * Xs[j * XS_PITCH + v];
        }
    }
    __syncthreads();

    float acc[4][4] = {};

    for (int cc = 0; cc < CHUNKS_PER_Z; cc++) {
        // Prefetch next D chunk (LDG latency hidden by the GEMM below).
        if (cc + 1 < CHUNKS_PER_Z) {
            const float* src = Dk + (size_t)(c0 + cc + 1) * 64 * DC_PITCH;
#pragma unroll
            for (int s = 0; s < 8; s++) dst[s] = src[t + 256 * s];
        }

        // Register-tile GEMM over this chunk's 64 pairs.
#pragma unroll 4
        for (int pp = 0; pp < 64; pp += 4) {
            const float4 d0 = *(const float4*)(Dc + (pp + 0) * DC_PITCH + lbase);
            const float4 d1 = *(const float4*)(Dc + (pp + 1) * DC_PITCH + lbase);
            const float4 d2 = *(const float4*)(Dc + (pp + 2) * DC_PITCH + lbase);
            const float4 d3 = *(const float4*)(Dc + (pp + 3) * DC_PITCH + lbase);
#pragma unroll
            for (int m = 0; m < 4; m++) {
                const float4 p = *(const float4*)(Ps + (vg + 32 * m) * PS_PITCH + pp);
                FMA_L4(acc[m], p.x, d0);
                FMA_L4(acc[m], p.y, d1);
                FMA_L4(acc[m], p.z, d2);
                FMA_L4(acc[m], p.w, d3);
            }
        }

        __syncthreads();   // all reads of Dc/Ps done
        if (cc + 1 < CHUNKS_PER_Z) {
#pragma unroll
            for (int s = 0; s < 8; s++) Dc[t + 256 * s] = dst[s];
            const int pairBase = (c0 + cc + 1) * 64;
#pragma unroll 4
            for (int s = 0; s < 32; s++) {
                int idx = t + 256 * s;
                int v = idx & 127, pp = idx >> 7;
                unsigned ij = g_pairIJ[pairBase + pp];
                int i = (int)(ij >> 16), j = (int)(ij & 0xffff);
                Ps[v * PS_PITCH + pp] = Xs[i * XS_PITCH + v] * Xs[j * XS_PITCH + v];
            }
            __syncthreads();   // next chunk staged
        }
    }

    // Epilogue: accumulate into Post_cov_mats[v][k+1][l+1].
#pragma unroll
    for (int m = 0; m < 4; m++) {
        const int v = vbase + vg + 32 * m;
        if (v < NVQ) {
#pragma unroll
            for (int ll = 0; ll < 4; ll++) {
                const int l = lbase + ll;
                if (l < KM1) {
                    atomicAdd(out + MEAN_SZ + (size_t)v * (KTOT * KTOT)
                                  + (k + 1) * KTOT + (l + 1),
                              acc[m][ll]);
                }
            }
        }
    }
}

// ---------------------------------------------------------------------------
// kernel_launch: init -> mean -> pair table -> build D -> pair GEMM.
// Only kernel launches (graph-capturable, allocation-free).
// ---------------------------------------------------------------------------
extern "C" void kernel_launch(void* const* d_in, const int* in_sizes, int n_in,
                              void* d_out, int out_size) {
    const float* Xi  = (const float*)d_in[0];   // Xi_evals        (128*2000)
    const float* Wm  = (const float*)d_in[1];   // vec_W_post_mean (3840)
    const float* Cov = (const float*)d_in[2];   // vec_W_post_cov  (3840*3840)
    const float* Cmu = (const float*)d_in[3];   // C_mu            (2000)
    float* out = (float*)d_out;

    (void)in_sizes; (void)n_in; (void)out_size;

    const int covTot = NVQ * KTOT * KTOT;
    init_cov_kernel<<<(covTot + 255) / 256, 256>>>(out);
    mean_kernel<<<(NVQ * KTOT + 255) / 256, 256>>>(Xi, Wm, Cmu, out);

    pair_table_kernel<<<RDIM, RDIM>>>();

    const int dItems  = NPAIR * KM1;                 // one warp each
    const int dBlocks = (dItems * 32 + 255) / 256;   // 30960
    build_D_kernel<<<dBlocks, 256>>>(Cov);

    const int smemB = (RDIM * XS_PITCH + VT * PS_PITCH + 64 * DC_PITCH)
                      * (int)sizeof(float);          // 108544 B
    cudaFuncSetAttribute(cov_pair_kernel,
                         cudaFuncAttributeMaxDynamicSharedMemorySize, smemB);

    dim3 grid((NVQ + VT - 1) / VT, KM1, ZSPLIT);     // (16, 30, 3)
    cov_pair_kernel<<<grid, 256, smemB>>>(Xi, out);
}

// round 14
// speedup vs baseline: 1.6821x; 1.4616x over previous
#include <cuda_runtime.h>
#include <cstddef>

// Problem constants
#define NVQ     2000
#define RDIM    128
#define KM1     30
#define KTOT    31
#define COV_ROW 3840            // RDIM * KM1
#define NPAIR   8256            // 128*129/2 pairs (i >= j)
#define NCHUNK  129             // NPAIR / 64
#define ZSPLIT  3
#define CHUNKS_PER_Z 43         // 129 / 3
#define VT      128             // v per CTA tile
#define VPAD    2048            // padded v (16 tiles)
#define PS_PITCH 68             // smem Ps row pitch (64 + 4): banks 4v+pp
#define DC_PITCH 32
#define MEAN_SZ (NVQ * KTOT)

#define FMA_L4(Y, a, C) do {                      \
    (Y)[0] = fmaf((a), (C).x, (Y)[0]);            \
    (Y)[1] = fmaf((a), (C).y, (Y)[1]);            \
    (Y)[2] = fmaf((a), (C).z, (Y)[2]);            \
    (Y)[3] = fmaf((a), (C).w, (Y)[3]);            \
} while (0)

// Static device scratch (no runtime allocation).
__device__ float    g_D[(size_t)KM1 * NPAIR * DC_PITCH];        // ~31.7 MB
__device__ float    g_P[(size_t)NCHUNK * VPAD * 64];            // ~67.7 MB
__device__ unsigned g_pairIJ[NPAIR];                            // (i<<16)|j

// ---------------------------------------------------------------------------
// cp.async helpers
// ---------------------------------------------------------------------------
__device__ __forceinline__ void cp16(float* dst_smem, const float* src) {
    unsigned d = (unsigned)__cvta_generic_to_shared(dst_smem);
    asm volatile("cp.async.cg.shared.global [%0], [%1], 16;\n"
                 :: "r"(d), "l"(src));
}
__device__ __forceinline__ void cp_commit() {
    asm volatile("cp.async.commit_group;\n" ::: "memory");
}
template <int N>
__device__ __forceinline__ void cp_wait() {
    asm volatile("cp.async.wait_group %0;\n" :: "n"(N) : "memory");
}

// ---------------------------------------------------------------------------
// Zero cov region; set [v][0][0] = 0.5 (sigma2_mu). Borders stay zero.
// ---------------------------------------------------------------------------
__global__ void init_cov_kernel(float* __restrict__ out) {
    int idx = blockIdx.x * blockDim.x + threadIdx.x;
    const int total = NVQ * KTOT * KTOT;
    if (idx < total) {
        int q = idx % (KTOT * KTOT);
        out[MEAN_SZ + idx] = (q == 0) ? 0.5f : 0.0f;
    }
}

// ---------------------------------------------------------------------------
// Post_mean_coefs (2000 x 31). Negligible.
// ---------------------------------------------------------------------------
__global__ void mean_kernel(const float* __restrict__ Xi,
                            const float* __restrict__ Wm,
                            const float* __restrict__ Cmu,
                            float* __restrict__ out) {
    int idx = blockIdx.x * blockDim.x + threadIdx.x;
    if (idx >= NVQ * KTOT) return;
    int v = idx / KTOT;
    int c = idx - v * KTOT;
    if (c == 0) { out[idx] = Cmu[v]; return; }
    float s = 0.0f;
#pragma unroll 8
    for (int i = 0; i < RDIM; i++)
        s = fmaf(Xi[i * NVQ + v], Wm[i * KM1 + (c - 1)], s);
    out[idx] = s;
}

// ---------------------------------------------------------------------------
// Pair enumeration: pair p = i*(i+1)/2 + j, i >= j.
// ---------------------------------------------------------------------------
__global__ void pair_table_kernel() {
    int i = blockIdx.x;
    int j = threadIdx.x;
    if (j <= i)
        g_pairIJ[i * (i + 1) / 2 + j] = ((unsigned)i << 16) | (unsigned)j;
}

// ---------------------------------------------------------------------------
// Symmetrized D[k][pair][l] = C[(ik),(jl)] + (i!=j)*C[(jk),(il)].
// ---------------------------------------------------------------------------
__global__ void build_D_kernel(const float* __restrict__ Cov) {
    int gwarp = (blockIdx.x * blockDim.x + threadIdx.x) >> 5;
    int lane  = threadIdx.x & 31;
    if (gwarp >= NPAIR * KM1) return;
    int pair = gwarp / KM1;
    int k    = gwarp - pair * KM1;
    unsigned ij = g_pairIJ[pair];
    int i = (int)(ij >> 16);
    int j = (int)(ij & 0xffff);
    float v = 0.0f;
    if (lane < KM1) {
        v = Cov[(size_t)(i * KM1 + k) * COV_ROW + j * KM1 + lane];
        if (i != j)
            v += Cov[(size_t)(j * KM1 + k) * COV_ROW + i * KM1 + lane];
    }
    g_D[((size_t)k * NPAIR + pair) * DC_PITCH + lane] = v;
}

// ---------------------------------------------------------------------------
// Precompute P[chunk][v][pp] = x[v,i]*x[v,j], chunk-contiguous so the hot
// kernel's stage load is one contiguous 32 KB block per (chunk, vtile).
// Grid (NCHUNK, 16 vtiles), 256 threads. X tile lives in smem (pitch 129).
// ---------------------------------------------------------------------------
__global__ void build_P_kernel(const float* __restrict__ Xi) {
    extern __shared__ float Xs[];                 // [128 i][129]
    const int t     = threadIdx.x;
    const int c     = blockIdx.x;
    const int vbase = blockIdx.y * VT;

#pragma unroll 8
    for (int s = 0; s < (RDIM * VT) / 256; s++) {
        int idx = t + 256 * s;
        int i = idx >> 7, v = idx & 127;
        int gv = vbase + v;
        Xs[i * 129 + v] = (gv < NVQ) ? Xi[i * NVQ + gv] : 0.0f;
    }
    __syncthreads();

    float* dst = g_P + ((size_t)c * VPAD + vbase) * 64;
#pragma unroll 8
    for (int s = 0; s < (VT * 64) / 256; s++) {
        int idx = t + 256 * s;
        int pp = idx & 63, v = idx >> 6;          // lanes: consecutive pp -> coalesced STG
        unsigned ij = g_pairIJ[c * 64 + pp];
        int i = (int)(ij >> 16), j = (int)(ij & 0xffff);
        dst[v * 64 + pp] = Xs[i * 129 + v] * Xs[j * 129 + v];
    }
}

// ---------------------------------------------------------------------------
// Hot kernel: cov[v,k,l] = sum_p P[v,p] * D[k][p][l].
// Grid (16 vtiles, 30 k, 3 z) = 1440 CTAs, 128 threads.
// Per thread: 8v x 4l register tile (1.5 B smem / FMA -> FMA-bound).
// Chunks of 64 pairs double-buffered through smem via cp.async.
// ---------------------------------------------------------------------------
__global__ __launch_bounds__(128, 2)
void cov_pair_kernel(float* __restrict__ out) {
    extern __shared__ float smem[];
    // buffer b: Ps [128 v][PS_PITCH] then Dc [64 pp][32]
    const int BUFW = VT * PS_PITCH + 64 * DC_PITCH;   // 10752 floats

    const int t     = threadIdx.x;
    const int lg    = t & 7;                  // 8 l-groups of 4
    const int vg    = t >> 3;                 // 16 v-groups
    const int vbase = blockIdx.x * VT;
    const int k     = blockIdx.y;
    const int c0    = blockIdx.z * CHUNKS_PER_Z;
    const int lbase = lg * 4;

    const float* Dk = g_D + (size_t)k * NPAIR * DC_PITCH;

    // Issue one chunk's loads into buffer b (contiguous gmem -> pitched smem).
    auto issue = [&](int c, int b) {
        float* Ps = smem + b * BUFW;
        float* Dc = Ps + VT * PS_PITCH;
        const float* Psrc = g_P + ((size_t)c * VPAD + vbase) * 64;
        const float* Dsrc = Dk + (size_t)c * 64 * DC_PITCH;
#pragma unroll
        for (int s = 0; s < 16; s++) {        // 32 KB of P, 16B granules
            int u = t + 128 * s;              // 16B-unit index, 0..2047
            int v = u >> 4, q4 = u & 15;
            cp16(Ps + v * PS_PITCH + q4 * 4, Psrc + u * 4);
        }
#pragma unroll
        for (int s = 0; s < 4; s++) {         // 8 KB of D, contiguous
            int u = t + 128 * s;
            cp16(Dc + u * 4, Dsrc + u * 4);
        }
        cp_commit();
    };

    issue(c0, 0);

    float acc[8][4] = {};

    for (int cc = 0; cc < CHUNKS_PER_Z; cc++) {
        const int b = cc & 1;
        if (cc + 1 < CHUNKS_PER_Z) {
            issue(c0 + cc + 1, b ^ 1);
            cp_wait<1>();                     // chunk cc complete
        } else {
            cp_wait<0>();
        }
        __syncthreads();                      // all threads' async data visible

        const float* Ps = smem + b * BUFW;
        const float* Dc = Ps + VT * PS_PITCH;

#pragma unroll 4
        for (int pp = 0; pp < 64; pp += 4) {
            const float4 d0 = *(const float4*)(Dc + (pp + 0) * DC_PITCH + lbase);
            const float4 d1 = *(const float4*)(Dc + (pp + 1) * DC_PITCH + lbase);
            const float4 d2 = *(const float4*)(Dc + (pp + 2) * DC_PITCH + lbase);
            const float4 d3 = *(const float4*)(Dc + (pp + 3) * DC_PITCH + lbase);
#pragma unroll
            for (int m = 0; m < 8; m++) {
                const float4 p = *(const float4*)(Ps + (vg + 16 * m) * PS_PITCH + pp);
                FMA_L4(acc[m], p.x, d0);
                FMA_L4(acc[m], p.y, d1);
                FMA_L4(acc[m], p.z, d2);
                FMA_L4(acc[m], p.w, d3);
            }
        }
        __syncthreads();                      // reads done before buffer reuse
    }

    // Epilogue: accumulate into Post_cov_mats[v][k+1][l+1].
#pragma unroll
    for (int m = 0; m < 8; m++) {
        const int v = vbase + vg + 16 * m;
        if (v < NVQ) {
#pragma unroll
            for (int ll = 0; ll < 4; ll++) {
                const int l = lbase + ll;
                if (l < KM1) {
                    atomicAdd(out + MEAN_SZ + (size_t)v * (KTOT * KTOT)
                                  + (k + 1) * KTOT + (l + 1),
                              acc[m][ll]);
                }
            }
        }
    }
}

// ---------------------------------------------------------------------------
// kernel_launch (graph-capturable: kernel launches only).
// ---------------------------------------------------------------------------
extern "C" void kernel_launch(void* const* d_in, const int* in_sizes, int n_in,
                              void* d_out, int out_size) {
    const float* Xi  = (const float*)d_in[0];   // Xi_evals        (128*2000)
    const float* Wm  = (const float*)d_in[1];   // vec_W_post_mean (3840)
    const float* Cov = (const float*)d_in[2];   // vec_W_post_cov  (3840*3840)
    const float* Cmu = (const float*)d_in[3];   // C_mu            (2000)
    float* out = (float*)d_out;

    (void)in_sizes; (void)n_in; (void)out_size;

    const int covTot = NVQ * KTOT * KTOT;
    init_cov_kernel<<<(covTot + 255) / 256, 256>>>(out);
    mean_kernel<<<(NVQ * KTOT + 255) / 256, 256>>>(Xi, Wm, Cmu, out);

    pair_table_kernel<<<RDIM, RDIM>>>();

    const int dItems  = NPAIR * KM1;
    const int dBlocks = (dItems * 32 + 255) / 256;
    build_D_kernel<<<dBlocks, 256>>>(Cov);

    const int xsB = RDIM * 129 * (int)sizeof(float);          // 66048 B
    cudaFuncSetAttribute(build_P_kernel,
                         cudaFuncAttributeMaxDynamicSharedMemorySize, xsB);
    dim3 pgrid(NCHUNK, (NVQ + VT - 1) / VT);                  // (129, 16)
    build_P_kernel<<<pgrid, 256, xsB>>>(Xi);

    const int hotB = 2 * (VT * PS_PITCH + 64 * DC_PITCH) * (int)sizeof(float); // 86016 B
    cudaFuncSetAttribute(cov_pair_kernel,
                         cudaFuncAttributeMaxDynamicSharedMemorySize, hotB);
    dim3 grid((NVQ + VT - 1) / VT, KM1, ZSPLIT);              // (16, 30, 3)
    cov_pair_kernel<<<grid, 128, hotB>>>(out);
}